// round 3
// baseline (speedup 1.0000x reference)
#include <cuda_runtime.h>
#include <cuda_bf16.h>
#include <cstddef>

// Problem constants
#define NB   8
#define CT   1024
#define LL   1024
#define HEADS 16
#define BN_EPS 1e-5f

// Scratch (static device allocations — allowed). Referenced ONLY from device code.
__device__ float g_k[NB * 512 * LL];     // 16 MB  [n][512][L] -> [n][16][32][L]
__device__ float g_q[NB * 512 * LL];     // 16 MB
__device__ float g_v[NB * 1024 * LL];    // 32 MB  [n][1024][L] -> [n][16][64][L]
__device__ float g_mid[NB * 1024 * LL];  // 32 MB  tokens + kqv

#define BUF_EXT 0
#define BUF_K   1
#define BUF_Q   2
#define BUF_V   3
#define BUF_MID 4

__device__ __forceinline__ float* pick_buf(int sel, float* ext) {
    switch (sel) {
        case BUF_K:   return g_k;
        case BUF_Q:   return g_q;
        case BUF_V:   return g_v;
        case BUF_MID: return g_mid;
        default:      return ext;
    }
}

// ---------------------------------------------------------------------------
// Grouped 1x1 conv + eval BatchNorm (+ optional residual add)
// out[n, co, l] = inv[co]*(W_g @ x_g)[co,l] + (b*inv + beta - mean*inv)[co] (+res)
// Input is always [N, CT, L]. Output is [N, cout_total, L] (COMPACT batch
// stride = cout_total*L, NOT CT*L — this was the R1/R2 OOB bug for cout=512).
// Tile: 64 cout x 128 L per block, 256 threads, cin chunked by 32.
// ---------------------------------------------------------------------------
__global__ __launch_bounds__(256) void conv_bn_kernel(
    const float* __restrict__ x_ext, const float* __restrict__ w,
    const float* __restrict__ bias, const float* __restrict__ gamma,
    const float* __restrict__ beta, const float* __restrict__ mean,
    const float* __restrict__ var,
    float* out_ext, int src_sel, int dst_sel, int use_residual,
    int cin_per_g, int cout_per_g, int cout_total)
{
    __shared__ float Xs[32][128];
    __shared__ float Ws[64][32];

    const float* x = pick_buf(src_sel, (float*)x_ext);
    float* out = pick_buf(dst_sel, out_ext);
    const float* residual = use_residual ? x : nullptr;

    const int n   = blockIdx.z;
    const int co0 = blockIdx.y * 64;
    const int l0  = blockIdx.x * 128;
    const int g   = co0 / cout_per_g;

    const float* xg = x + ((size_t)n * CT + (size_t)g * cin_per_g) * LL + l0;

    const int tid = threadIdx.x;
    const int tx = tid & 15;   // 16 -> 8 columns each
    const int ty = tid >> 4;   // 16 -> 4 rows each

    float acc[4][8];
#pragma unroll
    for (int i = 0; i < 4; i++)
#pragma unroll
        for (int j = 0; j < 8; j++) acc[i][j] = 0.f;

    const int nchunks = cin_per_g >> 5;
    for (int ch = 0; ch < nchunks; ch++) {
        // X chunk: 32 rows x 128 cols = 1024 float4, 4 per thread
#pragma unroll
        for (int i = 0; i < 4; i++) {
            int idx = tid + i * 256;
            int kk = idx >> 5, c4 = idx & 31;
            *(float4*)&Xs[kk][c4 * 4] =
                *(const float4*)(xg + (size_t)(ch * 32 + kk) * LL + c4 * 4);
        }
        // W chunk: 64 rows x 32 cols = 512 float4, 2 per thread
#pragma unroll
        for (int i = 0; i < 2; i++) {
            int idx = tid + i * 256;
            int r = idx >> 3, k4 = idx & 7;
            *(float4*)&Ws[r][k4 * 4] =
                *(const float4*)(w + (size_t)(co0 + r) * cin_per_g + ch * 32 + k4 * 4);
        }
        __syncthreads();

#pragma unroll 8
        for (int k = 0; k < 32; k++) {
            float4 x0 = *(const float4*)&Xs[k][tx * 8];
            float4 x1 = *(const float4*)&Xs[k][tx * 8 + 4];
            float xv[8] = {x0.x, x0.y, x0.z, x0.w, x1.x, x1.y, x1.z, x1.w};
#pragma unroll
            for (int i = 0; i < 4; i++) {
                float wv = Ws[ty * 4 + i][k];
#pragma unroll
                for (int j = 0; j < 8; j++) acc[i][j] += wv * xv[j];
            }
        }
        __syncthreads();
    }

#pragma unroll
    for (int i = 0; i < 4; i++) {
        int co = co0 + ty * 4 + i;
        float inv = gamma[co] * rsqrtf(var[co] + BN_EPS);
        float sh  = bias[co] * inv + beta[co] - mean[co] * inv;
        size_t base = ((size_t)n * cout_total + co) * LL + l0 + tx * 8;
#pragma unroll
        for (int j = 0; j < 8; j++) {
            float v = acc[i][j] * inv + sh;
            if (residual) v += residual[base + j];
            out[base + j] = v;
        }
    }
}

// ---------------------------------------------------------------------------
// Fused attention: per (n, h, q-tile of 128)
//   S = K^T Q (d=32), softmax over k (online, scaled by 1/32), O = V @ P
//   g_mid = tokens + O / l
// 512 threads. Dynamic smem: Qs 16K + Ks 16K + Vs 32K + P 64K + stats.
// ---------------------------------------------------------------------------
#define ATTN_SMEM_FLOATS (32*128 + 32*128 + 64*128 + 128*128 + 128 + 128)

__global__ __launch_bounds__(512) void attn_kernel(
    const float* __restrict__ tokens)
{
    extern __shared__ float sm[];
    float* Qs    = sm;                 // [32][128]
    float* Ks    = Qs + 32 * 128;      // [32][128]
    float* Vs    = Ks + 32 * 128;      // [64][128]
    float* P     = Vs + 64 * 128;      // [128][128]
    float* alpha = P + 128 * 128;      // [128]
    float* lsum  = alpha + 128;        // [128]

    const int n = blockIdx.z, h = blockIdx.y, q0 = blockIdx.x * 128;
    const int tid = threadIdx.x;
    const int tx = tid & 15;           // 16 -> 8 q columns each
    const int ty = tid >> 4;           // 32

    const float* Kg = g_k + ((size_t)n * HEADS + h) * 32 * LL;
    const float* Qg = g_q + ((size_t)n * HEADS + h) * 32 * LL;
    const float* Vg = g_v + ((size_t)n * HEADS + h) * 64 * LL;

    // Q tile: 32x128 = 1024 float4, 2 per thread
#pragma unroll
    for (int i = 0; i < 2; i++) {
        int idx = tid + i * 512;
        int r = idx >> 5, c4 = idx & 31;
        *(float4*)&Qs[r * 128 + c4 * 4] = *(const float4*)(Qg + (size_t)r * LL + q0 + c4 * 4);
    }

    float m_run = -1e30f, l_run = 0.f;  // valid for tid < 128
    float oacc[2][8];
#pragma unroll
    for (int i = 0; i < 2; i++)
#pragma unroll
        for (int j = 0; j < 8; j++) oacc[i][j] = 0.f;

    for (int kt = 0; kt < 8; kt++) {
        const int k0 = kt * 128;
        __syncthreads();  // previous iter's consumers done before overwrite
        // K tile 32x128 (2 f4/thread), V tile 64x128 (4 f4/thread)
#pragma unroll
        for (int i = 0; i < 2; i++) {
            int idx = tid + i * 512;
            int r = idx >> 5, c4 = idx & 31;
            *(float4*)&Ks[r * 128 + c4 * 4] = *(const float4*)(Kg + (size_t)r * LL + k0 + c4 * 4);
        }
#pragma unroll
        for (int i = 0; i < 4; i++) {
            int idx = tid + i * 512;
            int r = idx >> 5, c4 = idx & 31;
            *(float4*)&Vs[r * 128 + c4 * 4] = *(const float4*)(Vg + (size_t)r * LL + k0 + c4 * 4);
        }
        __syncthreads();

        // GEMM1: S[k][q] = sum_d K[d][k]*Q[d][q];  rows ty*4..+3, cols tx*8..+7
        {
            float s_[4][8];
#pragma unroll
            for (int i = 0; i < 4; i++)
#pragma unroll
                for (int j = 0; j < 8; j++) s_[i][j] = 0.f;
#pragma unroll 8
            for (int d = 0; d < 32; d++) {
                float4 a0 = *(const float4*)&Qs[d * 128 + tx * 8];
                float4 a1 = *(const float4*)&Qs[d * 128 + tx * 8 + 4];
                float qv[8] = {a0.x, a0.y, a0.z, a0.w, a1.x, a1.y, a1.z, a1.w};
#pragma unroll
                for (int i = 0; i < 4; i++) {
                    float kv = Ks[d * 128 + ty * 4 + i];
#pragma unroll
                    for (int j = 0; j < 8; j++) s_[i][j] += kv * qv[j];
                }
            }
            const float sc = 1.0f / 32.0f;  // 1/sqrt(L)
#pragma unroll
            for (int i = 0; i < 4; i++) {
                float* row = &P[(ty * 4 + i) * 128 + tx * 8];
#pragma unroll
                for (int j = 0; j < 8; j++) row[j] = s_[i][j] * sc;
            }
        }
        __syncthreads();

        // Online softmax per q column (one thread per column)
        if (tid < 128) {
            const int q = tid;
            float mx = m_run;
#pragma unroll 8
            for (int k = 0; k < 128; k++) mx = fmaxf(mx, P[k * 128 + q]);
            float a = __expf(m_run - mx);
            float ls = l_run * a;
#pragma unroll 8
            for (int k = 0; k < 128; k++) {
                float p = __expf(P[k * 128 + q] - mx);
                P[k * 128 + q] = p;
                ls += p;
            }
            m_run = mx; l_run = ls;
            alpha[q] = a;
        }
        __syncthreads();

        // GEMM2: O[d][q] = O*alpha + V @ P;  rows d = ty*2, ty*2+1
        {
            float al[8];
#pragma unroll
            for (int j = 0; j < 8; j++) al[j] = alpha[tx * 8 + j];
#pragma unroll
            for (int i = 0; i < 2; i++)
#pragma unroll
                for (int j = 0; j < 8; j++) oacc[i][j] *= al[j];
#pragma unroll 4
            for (int k = 0; k < 128; k++) {
                float v0 = Vs[(ty * 2) * 128 + k];
                float v1 = Vs[(ty * 2 + 1) * 128 + k];
                float4 p0 = *(const float4*)&P[k * 128 + tx * 8];
                float4 p1 = *(const float4*)&P[k * 128 + tx * 8 + 4];
                float pv[8] = {p0.x, p0.y, p0.z, p0.w, p1.x, p1.y, p1.z, p1.w};
#pragma unroll
                for (int j = 0; j < 8; j++) {
                    oacc[0][j] += v0 * pv[j];
                    oacc[1][j] += v1 * pv[j];
                }
            }
        }
    }

    if (tid < 128) lsum[tid] = l_run;
    __syncthreads();

    {
        float linv[8];
#pragma unroll
        for (int j = 0; j < 8; j++) linv[j] = 1.0f / lsum[tx * 8 + j];
        size_t base = ((size_t)n * CT + (size_t)h * 64) * LL + q0;
#pragma unroll
        for (int i = 0; i < 2; i++) {
            size_t rowb = base + (size_t)(ty * 2 + i) * LL + tx * 8;
#pragma unroll
            for (int j = 0; j < 8; j++)
                g_mid[rowb + j] = tokens[rowb + j] + oacc[i][j] * linv[j];
        }
    }
}

// ---------------------------------------------------------------------------
extern "C" void kernel_launch(void* const* d_in, const int* in_sizes, int n_in,
                              void* d_out, int out_size)
{
    (void)in_sizes; (void)n_in; (void)out_size;
    const float* tokens = (const float*)d_in[0];
    const float* kw = (const float*)d_in[1];
    const float* kb = (const float*)d_in[2];
    const float* kg = (const float*)d_in[3];
    const float* kbe = (const float*)d_in[4];
    const float* km = (const float*)d_in[5];
    const float* kvv = (const float*)d_in[6];
    const float* qw = (const float*)d_in[7];
    const float* qb = (const float*)d_in[8];
    const float* qg = (const float*)d_in[9];
    const float* qbe = (const float*)d_in[10];
    const float* qm = (const float*)d_in[11];
    const float* qvv = (const float*)d_in[12];
    const float* vw = (const float*)d_in[13];
    const float* vb = (const float*)d_in[14];
    const float* vg = (const float*)d_in[15];
    const float* vbe = (const float*)d_in[16];
    const float* vm = (const float*)d_in[17];
    const float* vvv = (const float*)d_in[18];
    const float* fw = (const float*)d_in[19];
    const float* fb = (const float*)d_in[20];
    const float* fg = (const float*)d_in[21];
    const float* fbe = (const float*)d_in[22];
    const float* fm = (const float*)d_in[23];
    const float* fvv = (const float*)d_in[24];

    // K, Q: cout=512, groups=8 (cout_per_g=64, cin_per_g=128)
    conv_bn_kernel<<<dim3(8, 8, 8), 256>>>(tokens, kw, kb, kg, kbe, km, kvv,
                                           nullptr, BUF_EXT, BUF_K, 0, 128, 64, 512);
    conv_bn_kernel<<<dim3(8, 8, 8), 256>>>(tokens, qw, qb, qg, qbe, qm, qvv,
                                           nullptr, BUF_EXT, BUF_Q, 0, 128, 64, 512);
    // V: cout=1024, groups=8 (cout_per_g=128)
    conv_bn_kernel<<<dim3(8, 16, 8), 256>>>(tokens, vw, vb, vg, vbe, vm, vvv,
                                            nullptr, BUF_EXT, BUF_V, 0, 128, 128, 1024);

    // Attention + residual -> g_mid
    const int attn_smem = ATTN_SMEM_FLOATS * (int)sizeof(float);
    cudaFuncSetAttribute(attn_kernel, cudaFuncAttributeMaxDynamicSharedMemorySize,
                         attn_smem);
    attn_kernel<<<dim3(8, HEADS, 8), 512, attn_smem>>>(tokens);

    // FF conv (groups=1) + residual: g_mid -> d_out
    conv_bn_kernel<<<dim3(8, 16, 8), 256>>>(nullptr, fw, fb, fg, fbe, fm, fvv,
                                            (float*)d_out, BUF_MID, BUF_EXT, 1,
                                            1024, 1024, 1024);
}

// round 5
// speedup vs baseline: 2.5240x; 2.5240x over previous
#include <cuda_runtime.h>
#include <cuda_bf16.h>
#include <cstdint>
#include <cstddef>

// Problem constants
#define NB    8
#define CT    1024
#define LL    1024
#define HEADS 16
#define BN_EPS 1e-5f

// ---------------------------------------------------------------------------
// Scratch (static device allocations). Referenced ONLY from device code.
// ---------------------------------------------------------------------------
__device__ __nv_bfloat16 g_kT[(size_t)NB * HEADS * LL * 32];  // 8 MB  [n][h][l][32d]
__device__ __nv_bfloat16 g_qT[(size_t)NB * HEADS * LL * 32];  // 8 MB  [n][h][l][32d]
__device__ __nv_bfloat16 g_vB[(size_t)NB * CT * LL];          // 16 MB [n][c][l] == per-head [d][k]
__device__ float         g_mid[(size_t)NB * CT * LL];         // 32 MB tokens + kqv

// conv output modes
#define OUT_F32 0
#define OUT_KT  1
#define OUT_QT  2
#define OUT_VB  3

// ---------------------------------------------------------------------------
// mma.sync / ldmatrix helpers (base PTX, sm_80+; compiles for compute_103)
// ---------------------------------------------------------------------------
__device__ __forceinline__ uint32_t smem_u32(const void* p) {
    uint32_t a;
    asm("{ .reg .u64 t; cvta.to.shared.u64 t, %1; cvt.u32.u64 %0, t; }"
        : "=r"(a) : "l"(p));
    return a;
}

#define LDSM_X4(R, A)                                                        \
    asm volatile("ldmatrix.sync.aligned.m8n8.x4.shared.b16 {%0,%1,%2,%3}, [%4];" \
                 : "=r"((R)[0]), "=r"((R)[1]), "=r"((R)[2]), "=r"((R)[3])    \
                 : "r"(A))

#define MMA16816(C, A, B0, B1)                                               \
    asm volatile("mma.sync.aligned.m16n8k16.row.col.f32.bf16.bf16.f32 "      \
                 "{%0,%1,%2,%3}, {%4,%5,%6,%7}, {%8,%9}, {%0,%1,%2,%3};"     \
                 : "+f"((C)[0]), "+f"((C)[1]), "+f"((C)[2]), "+f"((C)[3])    \
                 : "r"((A)[0]), "r"((A)[1]), "r"((A)[2]), "r"((A)[3]),       \
                   "r"(B0), "r"(B1))

__device__ __forceinline__ uint32_t packbf2(float x, float y) {
    __nv_bfloat162 t = __floats2bfloat162_rn(x, y);
    return *(uint32_t*)&t;
}

// ---------------------------------------------------------------------------
// Grouped 1x1 conv + eval BatchNorm. Input always [N, CT, L] fp32.
// Output mode:
//   OUT_F32: fp32 [N, cout_total, L] to out_ext (+ residual = src)
//   OUT_KT/OUT_QT: bf16 transposed [n][h][l][32] to g_kT / g_qT
//   OUT_VB: bf16 [n][co][l] to g_vB
// ---------------------------------------------------------------------------
__global__ __launch_bounds__(256) void conv_bn_kernel(
    const float* __restrict__ x_ext, const float* __restrict__ w,
    const float* __restrict__ bias, const float* __restrict__ gamma,
    const float* __restrict__ beta, const float* __restrict__ mean,
    const float* __restrict__ var,
    float* out_ext, int use_mid_src, int mode, int use_residual,
    int cin_per_g, int cout_per_g, int cout_total)
{
    __shared__ float Xs[32][128];
    __shared__ float Ws[64][32];

    const float* x = use_mid_src ? g_mid : x_ext;

    const int n   = blockIdx.z;
    const int co0 = blockIdx.y * 64;
    const int l0  = blockIdx.x * 128;
    const int g   = co0 / cout_per_g;

    const float* xg = x + ((size_t)n * CT + (size_t)g * cin_per_g) * LL + l0;

    const int tid = threadIdx.x;
    const int tx = tid & 15;   // 16 -> 8 columns each
    const int ty = tid >> 4;   // 16 -> 4 rows each

    float acc[4][8];
#pragma unroll
    for (int i = 0; i < 4; i++)
#pragma unroll
        for (int j = 0; j < 8; j++) acc[i][j] = 0.f;

    const int nchunks = cin_per_g >> 5;
    for (int ch = 0; ch < nchunks; ch++) {
#pragma unroll
        for (int i = 0; i < 4; i++) {
            int idx = tid + i * 256;
            int kk = idx >> 5, c4 = idx & 31;
            *(float4*)&Xs[kk][c4 * 4] =
                *(const float4*)(xg + (size_t)(ch * 32 + kk) * LL + c4 * 4);
        }
#pragma unroll
        for (int i = 0; i < 2; i++) {
            int idx = tid + i * 256;
            int r = idx >> 3, k4 = idx & 7;
            *(float4*)&Ws[r][k4 * 4] =
                *(const float4*)(w + (size_t)(co0 + r) * cin_per_g + ch * 32 + k4 * 4);
        }
        __syncthreads();

#pragma unroll 8
        for (int k = 0; k < 32; k++) {
            float4 x0 = *(const float4*)&Xs[k][tx * 8];
            float4 x1 = *(const float4*)&Xs[k][tx * 8 + 4];
            float xv[8] = {x0.x, x0.y, x0.z, x0.w, x1.x, x1.y, x1.z, x1.w};
#pragma unroll
            for (int i = 0; i < 4; i++) {
                float wv = Ws[ty * 4 + i][k];
#pragma unroll
                for (int j = 0; j < 8; j++) acc[i][j] += wv * xv[j];
            }
        }
        __syncthreads();
    }

#pragma unroll
    for (int i = 0; i < 4; i++) {
        int co = co0 + ty * 4 + i;
        float inv = gamma[co] * rsqrtf(var[co] + BN_EPS);
        float sh  = bias[co] * inv + beta[co] - mean[co] * inv;
        if (mode == OUT_F32) {
            size_t base = ((size_t)n * cout_total + co) * LL + l0 + tx * 8;
#pragma unroll
            for (int j = 0; j < 8; j++) {
                float v = acc[i][j] * inv + sh;
                if (use_residual) v += x[base + j];
                out_ext[base + j] = v;
            }
        } else if (mode == OUT_VB) {
            size_t base = ((size_t)n * cout_total + co) * LL + l0 + tx * 8;
#pragma unroll
            for (int j = 0; j < 8; j++)
                g_vB[base + j] = __float2bfloat16(acc[i][j] * inv + sh);
        } else {  // OUT_KT / OUT_QT: [n][h][l][32]
            __nv_bfloat16* dst = (mode == OUT_KT) ? g_kT : g_qT;
            int hh = co >> 5, d = co & 31;
            size_t base = (((size_t)n * HEADS + hh) * LL + l0 + tx * 8) * 32 + d;
#pragma unroll
            for (int j = 0; j < 8; j++)
                dst[base + (size_t)j * 32] = __float2bfloat16(acc[i][j] * inv + sh);
        }
    }
}

// ---------------------------------------------------------------------------
// Attention via mma.sync bf16 (HMMA). Block = (q-tile 128, h, n), 256 thr.
// Warp w owns q rows [w*16, w*16+16). Per 128-k chunk:
//   S = Q K^T (d=32) -> fragments; p = exp(S/32) (no max-sub, scores small);
//   accumulator fragments repacked directly as A fragments (FA2 trick);
//   O += P V (V fragments via non-trans ldmatrix from [d][k] layout).
// Final: out = tokens + O / rowsum(p).
// ---------------------------------------------------------------------------
#define QK_STRIDE 40   // bf16 elems per row (80 B) -> conflict-free ldmatrix
#define V_STRIDE  136  // bf16 elems per row (272 B)

__global__ __launch_bounds__(256) void attn_mma_kernel(
    const float* __restrict__ tokens)
{
    __shared__ alignas(16) __nv_bfloat16 Qs[128 * QK_STRIDE];
    __shared__ alignas(16) __nv_bfloat16 Ks[128 * QK_STRIDE];
    __shared__ alignas(16) __nv_bfloat16 Vs[64 * V_STRIDE];

    const int tid  = threadIdx.x;
    const int w    = tid >> 5;
    const int lane = tid & 31;
    const int grp  = lane >> 2;   // 0..7 (fragment row group)
    const int tg   = lane & 3;    // 0..3 (thread in group)
    const int q0   = blockIdx.x * 128;
    const int h    = blockIdx.y;
    const int n    = blockIdx.z;

    const uint32_t qs_b = smem_u32(Qs);
    const uint32_t ks_b = smem_u32(Ks);
    const uint32_t vs_b = smem_u32(Vs);

    // ldmatrix lane row/col pattern (shared by all x4 loads here)
    const int rowoff = (lane & 7) + ((lane >> 4) & 1) * 8;
    const int colsel = (lane >> 3) & 1;   // 0 or 1 -> +16 bytes

    // --- Load Q tile [128 q][32 d] into smem (row stride 80 B) ---
    {
        int row = tid >> 1, half = tid & 1;
        const uint4* src = (const uint4*)(g_qT +
            (((size_t)n * HEADS + h) * LL + q0 + row) * 32 + half * 16);
        uint4* dst = (uint4*)((char*)Qs + row * 80 + half * 32);
        dst[0] = src[0];
        dst[1] = src[1];
    }
    __syncthreads();

    // --- Q fragments (chunk-invariant): a[kstep][4], kstep over d 0-15,16-31
    uint32_t qa[2][4];
    {
        int r = lane & 15, cb = (lane >> 4) * 16;
#pragma unroll
        for (int ks = 0; ks < 2; ks++) {
            uint32_t addr = qs_b + (uint32_t)((w * 16 + r) * 80 + ks * 32 + cb);
            LDSM_X4(qa[ks], addr);
        }
    }

    const float SC2 = 1.4426950408889634f / 32.0f;  // log2(e)/sqrt(L)
    float o[8][4];
#pragma unroll
    for (int i = 0; i < 8; i++)
#pragma unroll
        for (int j = 0; j < 4; j++) o[i][j] = 0.f;
    float rs0 = 0.f, rs1 = 0.f;   // rowsums for rows grp, grp+8

    for (int c = 0; c < 8; c++) {
        const int k0 = c * 128;
        if (c) __syncthreads();  // prior ldmatrix readers done

        // K chunk [128 k][32 d] (2 thr/row, 32 B each)
        {
            int row = tid >> 1, half = tid & 1;
            const uint4* src = (const uint4*)(g_kT +
                (((size_t)n * HEADS + h) * LL + k0 + row) * 32 + half * 16);
            uint4* dst = (uint4*)((char*)Ks + row * 80 + half * 32);
            dst[0] = src[0];
            dst[1] = src[1];
        }
        // V chunk [64 d][128 k] (4 thr/row, 64 B each)
        {
            int row = tid >> 2, quar = tid & 3;
            const uint4* src = (const uint4*)(g_vB +
                ((size_t)n * CT + h * 64 + row) * LL + k0 + quar * 32);
            uint4* dst = (uint4*)((char*)Vs + row * 272 + quar * 64);
            dst[0] = src[0];
            dst[1] = src[1];
            dst[2] = src[2];
            dst[3] = src[3];
        }
        __syncthreads();

        // --- GEMM1: S fragments s[16 ntiles][4], ntile = 8 k-cols ---
        float s[16][4];
#pragma unroll
        for (int i = 0; i < 16; i++)
#pragma unroll
            for (int j = 0; j < 4; j++) s[i][j] = 0.f;

#pragma unroll
        for (int np = 0; np < 8; np++) {        // pairs of ntiles (16 k-cols)
#pragma unroll
            for (int ks = 0; ks < 2; ks++) {
                uint32_t b[4];
                uint32_t addr = ks_b + (uint32_t)((np * 16 + rowoff) * 80
                                                  + ks * 32 + colsel * 16);
                LDSM_X4(b, addr);
                MMA16816(s[2 * np],     qa[ks], b[0], b[1]);
                MMA16816(s[2 * np + 1], qa[ks], b[2], b[3]);
            }
        }

        // --- exp + repack to A fragments, then GEMM2 into O ---
#pragma unroll
        for (int kk = 0; kk < 8; kk++) {   // k-steps of 16 within chunk
            float e0a = exp2f(s[2 * kk][0] * SC2);
            float e0b = exp2f(s[2 * kk][1] * SC2);
            float e0c = exp2f(s[2 * kk][2] * SC2);
            float e0d = exp2f(s[2 * kk][3] * SC2);
            float e1a = exp2f(s[2 * kk + 1][0] * SC2);
            float e1b = exp2f(s[2 * kk + 1][1] * SC2);
            float e1c = exp2f(s[2 * kk + 1][2] * SC2);
            float e1d = exp2f(s[2 * kk + 1][3] * SC2);
            rs0 += e0a + e0b + e1a + e1b;    // rows grp
            rs1 += e0c + e0d + e1c + e1d;    // rows grp+8
            uint32_t a[4];
            a[0] = packbf2(e0a, e0b);
            a[1] = packbf2(e0c, e0d);
            a[2] = packbf2(e1a, e1b);
            a[3] = packbf2(e1c, e1d);

#pragma unroll
            for (int dp = 0; dp < 4; dp++) {  // pairs of d-tiles (16 d)
                uint32_t b[4];
                uint32_t addr = vs_b + (uint32_t)((dp * 16 + rowoff) * 272
                                                  + kk * 32 + colsel * 16);
                LDSM_X4(b, addr);
                MMA16816(o[2 * dp],     a, b[0], b[1]);
                MMA16816(o[2 * dp + 1], a, b[2], b[3]);
            }
        }
    }

    // --- rowsum reduce within quad (threads sharing fragment rows) ---
    rs0 += __shfl_xor_sync(0xFFFFFFFF, rs0, 1);
    rs0 += __shfl_xor_sync(0xFFFFFFFF, rs0, 2);
    rs1 += __shfl_xor_sync(0xFFFFFFFF, rs1, 1);
    rs1 += __shfl_xor_sync(0xFFFFFFFF, rs1, 2);
    const float inv0 = 1.0f / rs0;
    const float inv1 = 1.0f / rs1;

    // --- write: g_mid = tokens + O/lsum ---
    const int qg0 = q0 + w * 16 + grp;
#pragma unroll
    for (int dt = 0; dt < 8; dt++) {
        int d = dt * 8 + tg * 2;
        size_t i00 = ((size_t)n * CT + h * 64 + d) * LL + qg0;
        size_t i01 = ((size_t)n * CT + h * 64 + d + 1) * LL + qg0;
        g_mid[i00]     = tokens[i00]     + o[dt][0] * inv0;
        g_mid[i01]     = tokens[i01]     + o[dt][1] * inv0;
        g_mid[i00 + 8] = tokens[i00 + 8] + o[dt][2] * inv1;
        g_mid[i01 + 8] = tokens[i01 + 8] + o[dt][3] * inv1;
    }
}

// ---------------------------------------------------------------------------
extern "C" void kernel_launch(void* const* d_in, const int* in_sizes, int n_in,
                              void* d_out, int out_size)
{
    (void)in_sizes; (void)n_in; (void)out_size;
    const float* tokens = (const float*)d_in[0];
    const float* kw = (const float*)d_in[1];
    const float* kb = (const float*)d_in[2];
    const float* kg = (const float*)d_in[3];
    const float* kbe = (const float*)d_in[4];
    const float* km = (const float*)d_in[5];
    const float* kvv = (const float*)d_in[6];
    const float* qw = (const float*)d_in[7];
    const float* qb = (const float*)d_in[8];
    const float* qg = (const float*)d_in[9];
    const float* qbe = (const float*)d_in[10];
    const float* qm = (const float*)d_in[11];
    const float* qvv = (const float*)d_in[12];
    const float* vw = (const float*)d_in[13];
    const float* vb = (const float*)d_in[14];
    const float* vg = (const float*)d_in[15];
    const float* vbe = (const float*)d_in[16];
    const float* vm = (const float*)d_in[17];
    const float* vvv = (const float*)d_in[18];
    const float* fw = (const float*)d_in[19];
    const float* fb = (const float*)d_in[20];
    const float* fg = (const float*)d_in[21];
    const float* fbe = (const float*)d_in[22];
    const float* fm = (const float*)d_in[23];
    const float* fvv = (const float*)d_in[24];

    // K, Q convs: cout=512, groups=8 -> transposed bf16 [n][h][l][32]
    conv_bn_kernel<<<dim3(8, 8, 8), 256>>>(tokens, kw, kb, kg, kbe, km, kvv,
                                           nullptr, 0, OUT_KT, 0, 128, 64, 512);
    conv_bn_kernel<<<dim3(8, 8, 8), 256>>>(tokens, qw, qb, qg, qbe, qm, qvv,
                                           nullptr, 0, OUT_QT, 0, 128, 64, 512);
    // V conv: cout=1024, groups=8 -> bf16 [n][c][l]
    conv_bn_kernel<<<dim3(8, 16, 8), 256>>>(tokens, vw, vb, vg, vbe, vm, vvv,
                                            nullptr, 0, OUT_VB, 0, 128, 128, 1024);

    // Attention + residual -> g_mid (static smem, no attribute calls)
    attn_mma_kernel<<<dim3(8, HEADS, 8), 256>>>(tokens);

    // FF conv (groups=1, fp32) + residual: g_mid -> d_out
    conv_bn_kernel<<<dim3(8, 16, 8), 256>>>(nullptr, fw, fb, fg, fbe, fm, fvv,
                                            (float*)d_out, 1, OUT_F32, 1,
                                            1024, 1024, 1024);
}

// round 6
// speedup vs baseline: 5.8644x; 2.3235x over previous
#include <cuda_runtime.h>
#include <cuda_bf16.h>
#include <cstdint>
#include <cstddef>

// Problem constants
#define NB    8
#define CT    1024
#define LL    1024
#define HEADS 16
#define BN_EPS 1e-5f

// ---------------------------------------------------------------------------
// Scratch (static device allocations). Referenced ONLY from device code.
// ---------------------------------------------------------------------------
__device__ __nv_bfloat16 g_kT[(size_t)NB * HEADS * LL * 32];  // 8 MB  [n][h][l][32d]
__device__ __nv_bfloat16 g_qT[(size_t)NB * HEADS * LL * 32];  // 8 MB  [n][h][l][32d]
__device__ __nv_bfloat16 g_vB[(size_t)NB * CT * LL];          // 16 MB [n][c][l] == per-head [d][k]
__device__ float         g_mid[(size_t)NB * CT * LL];         // 32 MB tokens + kqv

// conv output modes
#define OUT_F32 0
#define OUT_KT  1
#define OUT_QT  2
#define OUT_VB  3

// ---------------------------------------------------------------------------
// mma.sync / ldmatrix helpers (base PTX, sm_80+; compiles for compute_103)
// ---------------------------------------------------------------------------
__device__ __forceinline__ uint32_t smem_u32(const void* p) {
    uint32_t a;
    asm("{ .reg .u64 t; cvta.to.shared.u64 t, %1; cvt.u32.u64 %0, t; }"
        : "=r"(a) : "l"(p));
    return a;
}

#define LDSM_X4(R, A)                                                        \
    asm volatile("ldmatrix.sync.aligned.m8n8.x4.shared.b16 {%0,%1,%2,%3}, [%4];" \
                 : "=r"((R)[0]), "=r"((R)[1]), "=r"((R)[2]), "=r"((R)[3])    \
                 : "r"(A))

#define MMA16816(C, A, B0, B1)                                               \
    asm volatile("mma.sync.aligned.m16n8k16.row.col.f32.bf16.bf16.f32 "      \
                 "{%0,%1,%2,%3}, {%4,%5,%6,%7}, {%8,%9}, {%0,%1,%2,%3};"     \
                 : "+f"((C)[0]), "+f"((C)[1]), "+f"((C)[2]), "+f"((C)[3])    \
                 : "r"((A)[0]), "r"((A)[1]), "r"((A)[2]), "r"((A)[3]),       \
                   "r"(B0), "r"(B1))

#define MMA_TF32(C, A, B0, B1)                                               \
    asm volatile("mma.sync.aligned.m16n8k8.row.col.f32.tf32.tf32.f32 "       \
                 "{%0,%1,%2,%3}, {%4,%5,%6,%7}, {%8,%9}, {%0,%1,%2,%3};"     \
                 : "+f"((C)[0]), "+f"((C)[1]), "+f"((C)[2]), "+f"((C)[3])    \
                 : "r"((A)[0]), "r"((A)[1]), "r"((A)[2]), "r"((A)[3]),       \
                   "r"(B0), "r"(B1))

__device__ __forceinline__ uint32_t packbf2(float x, float y) {
    __nv_bfloat162 t = __floats2bfloat162_rn(x, y);
    return *(uint32_t*)&t;
}
__device__ __forceinline__ uint32_t f2tf(float f) {
    uint32_t r;
    asm("cvt.rna.tf32.f32 %0, %1;" : "=r"(r) : "f"(f));
    return r;
}

// ---------------------------------------------------------------------------
// Grouped 1x1 conv + BN via tf32 mma.sync.
// Block: CO_TILE cout x 128 L, 256 threads (8 warps = 2x4).
// Warp tile: (CO_TILE/2) co x 32 l; mma m16n8k8, K chunked by 32.
// Smem strides chosen for conflict-free fragment LDS:
//   Ws stride 36: bank = 4*grp + tg (32 distinct)
//   Xs stride 136: bank = 8*tg + grp (32 distinct)
// ---------------------------------------------------------------------------
template <int CO_TILE>
__global__ __launch_bounds__(256) void conv_mma_kernel(
    const float* __restrict__ x_ext, const float* __restrict__ w,
    const float* __restrict__ bias, const float* __restrict__ gamma,
    const float* __restrict__ beta, const float* __restrict__ mean,
    const float* __restrict__ var,
    float* out_ext, int use_mid_src, int mode, int use_residual,
    int cin_per_g, int cout_per_g, int cout_total)
{
    constexpr int MT = CO_TILE / 32;        // mtiles per warp
    __shared__ uint32_t Ws[CO_TILE * 36];   // [CO_TILE][32] pad->36
    __shared__ uint32_t Xs[32 * 136];       // [32 k][128 l] pad->136

    const float* x = use_mid_src ? g_mid : x_ext;

    const int n   = blockIdx.z;
    const int co0 = blockIdx.y * CO_TILE;
    const int l0  = blockIdx.x * 128;
    const int g   = co0 / cout_per_g;

    const float* xg = x + ((size_t)n * CT + (size_t)g * cin_per_g) * LL + l0;

    const int tid  = threadIdx.x;
    const int wrp  = tid >> 5;
    const int lane = tid & 31;
    const int grp  = lane >> 2;
    const int tg   = lane & 3;
    const int wm   = wrp >> 2;      // 0..1
    const int wn   = wrp & 3;       // 0..3

    float c[MT][4][4];
#pragma unroll
    for (int mt = 0; mt < MT; mt++)
#pragma unroll
        for (int nt = 0; nt < 4; nt++)
#pragma unroll
            for (int j = 0; j < 4; j++) c[mt][nt][j] = 0.f;

    const int nchunks = cin_per_g >> 5;
    for (int ch = 0; ch < nchunks; ch++) {
        // X chunk [32 k][128 l] -> tf32
#pragma unroll
        for (int i = 0; i < 4; i++) {
            int idx = tid + i * 256;
            int r = idx >> 5, c4 = idx & 31;
            float4 v = *(const float4*)(xg + (size_t)(ch * 32 + r) * LL + c4 * 4);
            uint4 t = {f2tf(v.x), f2tf(v.y), f2tf(v.z), f2tf(v.w)};
            *(uint4*)&Xs[r * 136 + c4 * 4] = t;
        }
        // W chunk [CO_TILE][32] -> tf32
#pragma unroll
        for (int i = 0; i < CO_TILE / 32; i++) {
            int idx = tid + i * 256;
            int r = idx >> 3, k4 = idx & 7;
            float4 v = *(const float4*)(w + (size_t)(co0 + r) * cin_per_g + ch * 32 + k4 * 4);
            uint4 t = {f2tf(v.x), f2tf(v.y), f2tf(v.z), f2tf(v.w)};
            *(uint4*)&Ws[r * 36 + k4 * 4] = t;
        }
        __syncthreads();

#pragma unroll
        for (int ks = 0; ks < 4; ks++) {
            uint32_t a[MT][4], b[4][2];
#pragma unroll
            for (int mt = 0; mt < MT; mt++) {
                int r0 = (wm * (CO_TILE / 2) + mt * 16 + grp) * 36 + ks * 8 + tg;
                a[mt][0] = Ws[r0];
                a[mt][1] = Ws[r0 + 8 * 36];
                a[mt][2] = Ws[r0 + 4];
                a[mt][3] = Ws[r0 + 8 * 36 + 4];
            }
#pragma unroll
            for (int nt = 0; nt < 4; nt++) {
                int xb = (ks * 8 + tg) * 136 + wn * 32 + nt * 8 + grp;
                b[nt][0] = Xs[xb];
                b[nt][1] = Xs[xb + 4 * 136];
            }
#pragma unroll
            for (int mt = 0; mt < MT; mt++)
#pragma unroll
                for (int nt = 0; nt < 4; nt++)
                    MMA_TF32(c[mt][nt], a[mt], b[nt][0], b[nt][1]);
        }
        __syncthreads();
    }

    // Epilogue: BN + mode-specific store
#pragma unroll
    for (int mt = 0; mt < MT; mt++) {
        int coA = co0 + wm * (CO_TILE / 2) + mt * 16 + grp;
        int coB = coA + 8;
        float invA = gamma[coA] * rsqrtf(var[coA] + BN_EPS);
        float shA  = bias[coA] * invA + beta[coA] - mean[coA] * invA;
        float invB = gamma[coB] * rsqrtf(var[coB] + BN_EPS);
        float shB  = bias[coB] * invB + beta[coB] - mean[coB] * invB;

#pragma unroll
        for (int nt = 0; nt < 4; nt++) {
            int col = l0 + wn * 32 + nt * 8 + tg * 2;
            float vA0 = c[mt][nt][0] * invA + shA;
            float vA1 = c[mt][nt][1] * invA + shA;
            float vB0 = c[mt][nt][2] * invB + shB;
            float vB1 = c[mt][nt][3] * invB + shB;

            if (mode == OUT_F32) {
                size_t iA = ((size_t)n * cout_total + coA) * LL + col;
                size_t iB = ((size_t)n * cout_total + coB) * LL + col;
                if (use_residual) {
                    vA0 += x[iA]; vA1 += x[iA + 1];
                    vB0 += x[iB]; vB1 += x[iB + 1];
                }
                *(float2*)&out_ext[iA] = make_float2(vA0, vA1);
                *(float2*)&out_ext[iB] = make_float2(vB0, vB1);
            } else if (mode == OUT_VB) {
                size_t iA = ((size_t)n * cout_total + coA) * LL + col;
                size_t iB = ((size_t)n * cout_total + coB) * LL + col;
                *(uint32_t*)&g_vB[iA] = packbf2(vA0, vA1);
                *(uint32_t*)&g_vB[iB] = packbf2(vB0, vB1);
            } else {  // OUT_KT / OUT_QT: [n][h][l][32]
                __nv_bfloat16* dst = (mode == OUT_KT) ? g_kT : g_qT;
                int hA = coA >> 5, dA = coA & 31;
                int hB = coB >> 5, dB = coB & 31;
                size_t bA = (((size_t)n * HEADS + hA) * LL + col) * 32 + dA;
                size_t bB = (((size_t)n * HEADS + hB) * LL + col) * 32 + dB;
                dst[bA]      = __float2bfloat16(vA0);
                dst[bA + 32] = __float2bfloat16(vA1);
                dst[bB]      = __float2bfloat16(vB0);
                dst[bB + 32] = __float2bfloat16(vB1);
            }
        }
    }
}

// ---------------------------------------------------------------------------
// Attention via mma.sync bf16 (HMMA). Block = (q-tile 128, h, n), 256 thr.
// (unchanged from R5 — measured 105 us)
// ---------------------------------------------------------------------------
#define QK_STRIDE 40   // bf16 elems per row (80 B) -> conflict-free ldmatrix
#define V_STRIDE  136  // bf16 elems per row (272 B)

__global__ __launch_bounds__(256) void attn_mma_kernel(
    const float* __restrict__ tokens)
{
    __shared__ alignas(16) __nv_bfloat16 Qs[128 * QK_STRIDE];
    __shared__ alignas(16) __nv_bfloat16 Ks[128 * QK_STRIDE];
    __shared__ alignas(16) __nv_bfloat16 Vs[64 * V_STRIDE];

    const int tid  = threadIdx.x;
    const int w    = tid >> 5;
    const int lane = tid & 31;
    const int grp  = lane >> 2;
    const int tg   = lane & 3;
    const int q0   = blockIdx.x * 128;
    const int h    = blockIdx.y;
    const int n    = blockIdx.z;

    const uint32_t qs_b = smem_u32(Qs);
    const uint32_t ks_b = smem_u32(Ks);
    const uint32_t vs_b = smem_u32(Vs);

    const int rowoff = (lane & 7) + ((lane >> 4) & 1) * 8;
    const int colsel = (lane >> 3) & 1;

    {
        int row = tid >> 1, half = tid & 1;
        const uint4* src = (const uint4*)(g_qT +
            (((size_t)n * HEADS + h) * LL + q0 + row) * 32 + half * 16);
        uint4* dst = (uint4*)((char*)Qs + row * 80 + half * 32);
        dst[0] = src[0];
        dst[1] = src[1];
    }
    __syncthreads();

    uint32_t qa[2][4];
    {
        int r = lane & 15, cb = (lane >> 4) * 16;
#pragma unroll
        for (int ks = 0; ks < 2; ks++) {
            uint32_t addr = qs_b + (uint32_t)((w * 16 + r) * 80 + ks * 32 + cb);
            LDSM_X4(qa[ks], addr);
        }
    }

    const float SC2 = 1.4426950408889634f / 32.0f;
    float o[8][4];
#pragma unroll
    for (int i = 0; i < 8; i++)
#pragma unroll
        for (int j = 0; j < 4; j++) o[i][j] = 0.f;
    float rs0 = 0.f, rs1 = 0.f;

    for (int c = 0; c < 8; c++) {
        const int k0 = c * 128;
        if (c) __syncthreads();

        {
            int row = tid >> 1, half = tid & 1;
            const uint4* src = (const uint4*)(g_kT +
                (((size_t)n * HEADS + h) * LL + k0 + row) * 32 + half * 16);
            uint4* dst = (uint4*)((char*)Ks + row * 80 + half * 32);
            dst[0] = src[0];
            dst[1] = src[1];
        }
        {
            int row = tid >> 2, quar = tid & 3;
            const uint4* src = (const uint4*)(g_vB +
                ((size_t)n * CT + h * 64 + row) * LL + k0 + quar * 32);
            uint4* dst = (uint4*)((char*)Vs + row * 272 + quar * 64);
            dst[0] = src[0];
            dst[1] = src[1];
            dst[2] = src[2];
            dst[3] = src[3];
        }
        __syncthreads();

        float s[16][4];
#pragma unroll
        for (int i = 0; i < 16; i++)
#pragma unroll
            for (int j = 0; j < 4; j++) s[i][j] = 0.f;

#pragma unroll
        for (int np = 0; np < 8; np++) {
#pragma unroll
            for (int ks = 0; ks < 2; ks++) {
                uint32_t b[4];
                uint32_t addr = ks_b + (uint32_t)((np * 16 + rowoff) * 80
                                                  + ks * 32 + colsel * 16);
                LDSM_X4(b, addr);
                MMA16816(s[2 * np],     qa[ks], b[0], b[1]);
                MMA16816(s[2 * np + 1], qa[ks], b[2], b[3]);
            }
        }

#pragma unroll
        for (int kk = 0; kk < 8; kk++) {
            float e0a = exp2f(s[2 * kk][0] * SC2);
            float e0b = exp2f(s[2 * kk][1] * SC2);
            float e0c = exp2f(s[2 * kk][2] * SC2);
            float e0d = exp2f(s[2 * kk][3] * SC2);
            float e1a = exp2f(s[2 * kk + 1][0] * SC2);
            float e1b = exp2f(s[2 * kk + 1][1] * SC2);
            float e1c = exp2f(s[2 * kk + 1][2] * SC2);
            float e1d = exp2f(s[2 * kk + 1][3] * SC2);
            rs0 += e0a + e0b + e1a + e1b;
            rs1 += e0c + e0d + e1c + e1d;
            uint32_t a[4];
            a[0] = packbf2(e0a, e0b);
            a[1] = packbf2(e0c, e0d);
            a[2] = packbf2(e1a, e1b);
            a[3] = packbf2(e1c, e1d);

#pragma unroll
            for (int dp = 0; dp < 4; dp++) {
                uint32_t b[4];
                uint32_t addr = vs_b + (uint32_t)((dp * 16 + rowoff) * 272
                                                  + kk * 32 + colsel * 16);
                LDSM_X4(b, addr);
                MMA16816(o[2 * dp],     a, b[0], b[1]);
                MMA16816(o[2 * dp + 1], a, b[2], b[3]);
            }
        }
    }

    rs0 += __shfl_xor_sync(0xFFFFFFFF, rs0, 1);
    rs0 += __shfl_xor_sync(0xFFFFFFFF, rs0, 2);
    rs1 += __shfl_xor_sync(0xFFFFFFFF, rs1, 1);
    rs1 += __shfl_xor_sync(0xFFFFFFFF, rs1, 2);
    const float inv0 = 1.0f / rs0;
    const float inv1 = 1.0f / rs1;

    const int qg0 = q0 + w * 16 + grp;
#pragma unroll
    for (int dt = 0; dt < 8; dt++) {
        int d = dt * 8 + tg * 2;
        size_t i00 = ((size_t)n * CT + h * 64 + d) * LL + qg0;
        size_t i01 = ((size_t)n * CT + h * 64 + d + 1) * LL + qg0;
        g_mid[i00]     = tokens[i00]     + o[dt][0] * inv0;
        g_mid[i01]     = tokens[i01]     + o[dt][1] * inv0;
        g_mid[i00 + 8] = tokens[i00 + 8] + o[dt][2] * inv1;
        g_mid[i01 + 8] = tokens[i01 + 8] + o[dt][3] * inv1;
    }
}

// ---------------------------------------------------------------------------
extern "C" void kernel_launch(void* const* d_in, const int* in_sizes, int n_in,
                              void* d_out, int out_size)
{
    (void)in_sizes; (void)n_in; (void)out_size;
    const float* tokens = (const float*)d_in[0];
    const float* kw = (const float*)d_in[1];
    const float* kb = (const float*)d_in[2];
    const float* kg = (const float*)d_in[3];
    const float* kbe = (const float*)d_in[4];
    const float* km = (const float*)d_in[5];
    const float* kvv = (const float*)d_in[6];
    const float* qw = (const float*)d_in[7];
    const float* qb = (const float*)d_in[8];
    const float* qg = (const float*)d_in[9];
    const float* qbe = (const float*)d_in[10];
    const float* qm = (const float*)d_in[11];
    const float* qvv = (const float*)d_in[12];
    const float* vw = (const float*)d_in[13];
    const float* vb = (const float*)d_in[14];
    const float* vg = (const float*)d_in[15];
    const float* vbe = (const float*)d_in[16];
    const float* vm = (const float*)d_in[17];
    const float* vvv = (const float*)d_in[18];
    const float* fw = (const float*)d_in[19];
    const float* fb = (const float*)d_in[20];
    const float* fg = (const float*)d_in[21];
    const float* fbe = (const float*)d_in[22];
    const float* fm = (const float*)d_in[23];
    const float* fvv = (const float*)d_in[24];

    // K, Q convs: cout=512, groups=8 -> transposed bf16 [n][h][l][32]
    conv_mma_kernel<64><<<dim3(8, 8, 8), 256>>>(tokens, kw, kb, kg, kbe, km, kvv,
                                                nullptr, 0, OUT_KT, 0, 128, 64, 512);
    conv_mma_kernel<64><<<dim3(8, 8, 8), 256>>>(tokens, qw, qb, qg, qbe, qm, qvv,
                                                nullptr, 0, OUT_QT, 0, 128, 64, 512);
    // V conv: cout=1024, groups=8 -> bf16 [n][c][l]
    conv_mma_kernel<128><<<dim3(8, 8, 8), 256>>>(tokens, vw, vb, vg, vbe, vm, vvv,
                                                 nullptr, 0, OUT_VB, 0, 128, 128, 1024);

    // Attention + residual -> g_mid
    attn_mma_kernel<<<dim3(8, HEADS, 8), 256>>>(tokens);

    // FF conv (groups=1, tf32) + residual: g_mid -> d_out
    conv_mma_kernel<128><<<dim3(8, 8, 8), 256>>>(nullptr, fw, fb, fg, fbe, fm, fvv,
                                                 (float*)d_out, 1, OUT_F32, 1,
                                                 1024, 1024, 1024);
}

// round 7
// speedup vs baseline: 7.4811x; 1.2757x over previous
#include <cuda_runtime.h>
#include <cuda_bf16.h>
#include <cstdint>
#include <cstddef>

// Problem constants
#define NB    8
#define CT    1024
#define LL    1024
#define HEADS 16
#define BN_EPS 1e-5f

// ---------------------------------------------------------------------------
// Scratch (static device allocations). Referenced ONLY from device code.
// ---------------------------------------------------------------------------
__device__ __nv_bfloat16 g_kT[(size_t)NB * HEADS * LL * 32];  // 8 MB  [n][h][l][32d]
__device__ __nv_bfloat16 g_qT[(size_t)NB * HEADS * LL * 32];  // 8 MB  [n][h][l][32d]
__device__ __nv_bfloat16 g_vB[(size_t)NB * CT * LL];          // 16 MB [n][c][l] == per-head [d][k]
__device__ float         g_mid[(size_t)NB * CT * LL];         // 32 MB tokens + kqv

// conv output modes
#define OUT_F32 0
#define OUT_KT  1
#define OUT_QT  2
#define OUT_VB  3

// ---------------------------------------------------------------------------
// mma.sync / ldmatrix / cp.async helpers (base PTX, sm_80+)
// ---------------------------------------------------------------------------
__device__ __forceinline__ uint32_t smem_u32(const void* p) {
    uint32_t a;
    asm("{ .reg .u64 t; cvta.to.shared.u64 t, %1; cvt.u32.u64 %0, t; }"
        : "=r"(a) : "l"(p));
    return a;
}

#define LDSM_X4(R, A)                                                        \
    asm volatile("ldmatrix.sync.aligned.m8n8.x4.shared.b16 {%0,%1,%2,%3}, [%4];" \
                 : "=r"((R)[0]), "=r"((R)[1]), "=r"((R)[2]), "=r"((R)[3])    \
                 : "r"(A))

#define MMA16816(C, A, B0, B1)                                               \
    asm volatile("mma.sync.aligned.m16n8k16.row.col.f32.bf16.bf16.f32 "      \
                 "{%0,%1,%2,%3}, {%4,%5,%6,%7}, {%8,%9}, {%0,%1,%2,%3};"     \
                 : "+f"((C)[0]), "+f"((C)[1]), "+f"((C)[2]), "+f"((C)[3])    \
                 : "r"((A)[0]), "r"((A)[1]), "r"((A)[2]), "r"((A)[3]),       \
                   "r"(B0), "r"(B1))

#define MMA_TF32(C, A, B0, B1)                                               \
    asm volatile("mma.sync.aligned.m16n8k8.row.col.f32.tf32.tf32.f32 "       \
                 "{%0,%1,%2,%3}, {%4,%5,%6,%7}, {%8,%9}, {%0,%1,%2,%3};"     \
                 : "+f"((C)[0]), "+f"((C)[1]), "+f"((C)[2]), "+f"((C)[3])    \
                 : "r"((A)[0]), "r"((A)[1]), "r"((A)[2]), "r"((A)[3]),       \
                   "r"(B0), "r"(B1))

#define CP_ASYNC16(smem, gptr)                                               \
    asm volatile("cp.async.cg.shared.global [%0], [%1], 16;"                 \
                 :: "r"(smem), "l"(gptr))
#define CP_COMMIT() asm volatile("cp.async.commit_group;" ::: "memory")
#define CP_WAIT(N)  asm volatile("cp.async.wait_group %0;" :: "n"(N) : "memory")

__device__ __forceinline__ uint32_t packbf2(float x, float y) {
    __nv_bfloat162 t = __floats2bfloat162_rn(x, y);
    return *(uint32_t*)&t;
}
__device__ __forceinline__ uint32_t f2tf(uint32_t bits) {
    uint32_t r;
    asm("cvt.rna.tf32.f32 %0, %1;" : "=r"(r) : "r"(bits));
    return r;
}

// ---------------------------------------------------------------------------
// Grouped 1x1 conv + BN via tf32 mma.sync with cp.async double buffering.
// Block: CO_TILE cout x 128 L, 256 threads (8 warps = 2x4).
// Warp tile: (CO_TILE/2) co x 32 l; mma m16n8k8, K chunked by 32, 2 stages.
// Smem strides conflict-free for fragment LDS (Ws pad 36, Xs pad 136).
// tf32 cvt happens at fragment-load time (cp.async lands raw fp32).
// ---------------------------------------------------------------------------
template <int CO_TILE>
__global__ __launch_bounds__(256) void conv_mma_kernel(
    const float* __restrict__ x_ext, const float* __restrict__ w,
    const float* __restrict__ bias, const float* __restrict__ gamma,
    const float* __restrict__ beta, const float* __restrict__ mean,
    const float* __restrict__ var,
    float* out_ext, int use_mid_src, int mode, int use_residual,
    int cin_per_g, int cout_per_g, int cout_total)
{
    constexpr int MT = CO_TILE / 32;        // mtiles per warp
    constexpr int WSZ = CO_TILE * 36;       // one W stage (u32)
    constexpr int XSZ = 32 * 136;           // one X stage (u32)
    extern __shared__ uint32_t dynsm[];
    uint32_t* Wsm = dynsm;                  // [2][WSZ]
    uint32_t* Xsm = dynsm + 2 * WSZ;        // [2][XSZ]
    const uint32_t ws_addr = smem_u32(Wsm);
    const uint32_t xs_addr = smem_u32(Xsm);

    const float* x = use_mid_src ? g_mid : x_ext;

    const int n   = blockIdx.z;
    const int co0 = blockIdx.y * CO_TILE;
    const int l0  = blockIdx.x * 128;
    const int g   = co0 / cout_per_g;

    const float* xg = x + ((size_t)n * CT + (size_t)g * cin_per_g) * LL + l0;

    const int tid  = threadIdx.x;
    const int wrp  = tid >> 5;
    const int lane = tid & 31;
    const int grp  = lane >> 2;
    const int tg   = lane & 3;
    const int wm   = wrp >> 2;      // 0..1
    const int wn   = wrp & 3;       // 0..3

    float c[MT][4][4];
#pragma unroll
    for (int mt = 0; mt < MT; mt++)
#pragma unroll
        for (int nt = 0; nt < 4; nt++)
#pragma unroll
            for (int j = 0; j < 4; j++) c[mt][nt][j] = 0.f;

    const int nchunks = cin_per_g >> 5;

    // --- async stage issue ---
    auto issue = [&](int ch, int buf) {
#pragma unroll
        for (int i = 0; i < 4; i++) {           // X: 32x128 = 1024 f4
            int idx = tid + i * 256;
            int r = idx >> 5, c4 = idx & 31;
            uint32_t dst = xs_addr + (uint32_t)(buf * XSZ + r * 136 + c4 * 4) * 4;
            CP_ASYNC16(dst, xg + (size_t)(ch * 32 + r) * LL + c4 * 4);
        }
#pragma unroll
        for (int i = 0; i < CO_TILE / 32; i++) {  // W: CO_TILE x 32
            int idx = tid + i * 256;
            int r = idx >> 3, k4 = idx & 7;
            uint32_t dst = ws_addr + (uint32_t)(buf * WSZ + r * 36 + k4 * 4) * 4;
            CP_ASYNC16(dst, w + (size_t)(co0 + r) * cin_per_g + ch * 32 + k4 * 4);
        }
        CP_COMMIT();
    };

    issue(0, 0);
    for (int ch = 0; ch < nchunks; ch++) {
        if (ch + 1 < nchunks) {
            issue(ch + 1, (ch + 1) & 1);
            CP_WAIT(1);
        } else {
            CP_WAIT(0);
        }
        __syncthreads();

        const uint32_t* Wb = Wsm + (ch & 1) * WSZ;
        const uint32_t* Xb = Xsm + (ch & 1) * XSZ;

#pragma unroll
        for (int ks = 0; ks < 4; ks++) {
            uint32_t a[MT][4], b[4][2];
#pragma unroll
            for (int mt = 0; mt < MT; mt++) {
                int r0 = (wm * (CO_TILE / 2) + mt * 16 + grp) * 36 + ks * 8 + tg;
                a[mt][0] = f2tf(Wb[r0]);
                a[mt][1] = f2tf(Wb[r0 + 8 * 36]);
                a[mt][2] = f2tf(Wb[r0 + 4]);
                a[mt][3] = f2tf(Wb[r0 + 8 * 36 + 4]);
            }
#pragma unroll
            for (int nt = 0; nt < 4; nt++) {
                int xb = (ks * 8 + tg) * 136 + wn * 32 + nt * 8 + grp;
                b[nt][0] = f2tf(Xb[xb]);
                b[nt][1] = f2tf(Xb[xb + 4 * 136]);
            }
#pragma unroll
            for (int mt = 0; mt < MT; mt++)
#pragma unroll
                for (int nt = 0; nt < 4; nt++)
                    MMA_TF32(c[mt][nt], a[mt], b[nt][0], b[nt][1]);
        }
        __syncthreads();
    }

    // Epilogue: BN + mode-specific store
#pragma unroll
    for (int mt = 0; mt < MT; mt++) {
        int coA = co0 + wm * (CO_TILE / 2) + mt * 16 + grp;
        int coB = coA + 8;
        float invA = gamma[coA] * rsqrtf(var[coA] + BN_EPS);
        float shA  = bias[coA] * invA + beta[coA] - mean[coA] * invA;
        float invB = gamma[coB] * rsqrtf(var[coB] + BN_EPS);
        float shB  = bias[coB] * invB + beta[coB] - mean[coB] * invB;

#pragma unroll
        for (int nt = 0; nt < 4; nt++) {
            int col = l0 + wn * 32 + nt * 8 + tg * 2;
            float vA0 = c[mt][nt][0] * invA + shA;
            float vA1 = c[mt][nt][1] * invA + shA;
            float vB0 = c[mt][nt][2] * invB + shB;
            float vB1 = c[mt][nt][3] * invB + shB;

            if (mode == OUT_F32) {
                size_t iA = ((size_t)n * cout_total + coA) * LL + col;
                size_t iB = ((size_t)n * cout_total + coB) * LL + col;
                if (use_residual) {
                    vA0 += x[iA]; vA1 += x[iA + 1];
                    vB0 += x[iB]; vB1 += x[iB + 1];
                }
                *(float2*)&out_ext[iA] = make_float2(vA0, vA1);
                *(float2*)&out_ext[iB] = make_float2(vB0, vB1);
            } else if (mode == OUT_VB) {
                size_t iA = ((size_t)n * cout_total + coA) * LL + col;
                size_t iB = ((size_t)n * cout_total + coB) * LL + col;
                *(uint32_t*)&g_vB[iA] = packbf2(vA0, vA1);
                *(uint32_t*)&g_vB[iB] = packbf2(vB0, vB1);
            } else {  // OUT_KT / OUT_QT: [n][h][l][32]
                __nv_bfloat16* dst = (mode == OUT_KT) ? g_kT : g_qT;
                int hA = coA >> 5, dA = coA & 31;
                int hB = coB >> 5, dB = coB & 31;
                size_t bA = (((size_t)n * HEADS + hA) * LL + col) * 32 + dA;
                size_t bB = (((size_t)n * HEADS + hB) * LL + col) * 32 + dB;
                dst[bA]      = __float2bfloat16(vA0);
                dst[bA + 32] = __float2bfloat16(vA1);
                dst[bB]      = __float2bfloat16(vB0);
                dst[bB + 32] = __float2bfloat16(vB1);
            }
        }
    }
}

// ---------------------------------------------------------------------------
// Attention via mma.sync bf16 (HMMA). Block = (q-tile 128, h, n), 256 thr.
// (unchanged from R5/R6 — measured 105 us)
// ---------------------------------------------------------------------------
#define QK_STRIDE 40   // bf16 elems per row (80 B) -> conflict-free ldmatrix
#define V_STRIDE  136  // bf16 elems per row (272 B)

__global__ __launch_bounds__(256) void attn_mma_kernel(
    const float* __restrict__ tokens)
{
    __shared__ alignas(16) __nv_bfloat16 Qs[128 * QK_STRIDE];
    __shared__ alignas(16) __nv_bfloat16 Ks[128 * QK_STRIDE];
    __shared__ alignas(16) __nv_bfloat16 Vs[64 * V_STRIDE];

    const int tid  = threadIdx.x;
    const int w    = tid >> 5;
    const int lane = tid & 31;
    const int grp  = lane >> 2;
    const int tg   = lane & 3;
    const int q0   = blockIdx.x * 128;
    const int h    = blockIdx.y;
    const int n    = blockIdx.z;

    const uint32_t qs_b = smem_u32(Qs);
    const uint32_t ks_b = smem_u32(Ks);
    const uint32_t vs_b = smem_u32(Vs);

    const int rowoff = (lane & 7) + ((lane >> 4) & 1) * 8;
    const int colsel = (lane >> 3) & 1;

    {
        int row = tid >> 1, half = tid & 1;
        const uint4* src = (const uint4*)(g_qT +
            (((size_t)n * HEADS + h) * LL + q0 + row) * 32 + half * 16);
        uint4* dst = (uint4*)((char*)Qs + row * 80 + half * 32);
        dst[0] = src[0];
        dst[1] = src[1];
    }
    __syncthreads();

    uint32_t qa[2][4];
    {
        int r = lane & 15, cb = (lane >> 4) * 16;
#pragma unroll
        for (int ks = 0; ks < 2; ks++) {
            uint32_t addr = qs_b + (uint32_t)((w * 16 + r) * 80 + ks * 32 + cb);
            LDSM_X4(qa[ks], addr);
        }
    }

    const float SC2 = 1.4426950408889634f / 32.0f;
    float o[8][4];
#pragma unroll
    for (int i = 0; i < 8; i++)
#pragma unroll
        for (int j = 0; j < 4; j++) o[i][j] = 0.f;
    float rs0 = 0.f, rs1 = 0.f;

    for (int c = 0; c < 8; c++) {
        const int k0 = c * 128;
        if (c) __syncthreads();

        {
            int row = tid >> 1, half = tid & 1;
            const uint4* src = (const uint4*)(g_kT +
                (((size_t)n * HEADS + h) * LL + k0 + row) * 32 + half * 16);
            uint4* dst = (uint4*)((char*)Ks + row * 80 + half * 32);
            dst[0] = src[0];
            dst[1] = src[1];
        }
        {
            int row = tid >> 2, quar = tid & 3;
            const uint4* src = (const uint4*)(g_vB +
                ((size_t)n * CT + h * 64 + row) * LL + k0 + quar * 32);
            uint4* dst = (uint4*)((char*)Vs + row * 272 + quar * 64);
            dst[0] = src[0];
            dst[1] = src[1];
            dst[2] = src[2];
            dst[3] = src[3];
        }
        __syncthreads();

        float s[16][4];
#pragma unroll
        for (int i = 0; i < 16; i++)
#pragma unroll
            for (int j = 0; j < 4; j++) s[i][j] = 0.f;

#pragma unroll
        for (int np = 0; np < 8; np++) {
#pragma unroll
            for (int ks = 0; ks < 2; ks++) {
                uint32_t b[4];
                uint32_t addr = ks_b + (uint32_t)((np * 16 + rowoff) * 80
                                                  + ks * 32 + colsel * 16);
                LDSM_X4(b, addr);
                MMA16816(s[2 * np],     qa[ks], b[0], b[1]);
                MMA16816(s[2 * np + 1], qa[ks], b[2], b[3]);
            }
        }

#pragma unroll
        for (int kk = 0; kk < 8; kk++) {
            float e0a = exp2f(s[2 * kk][0] * SC2);
            float e0b = exp2f(s[2 * kk][1] * SC2);
            float e0c = exp2f(s[2 * kk][2] * SC2);
            float e0d = exp2f(s[2 * kk][3] * SC2);
            float e1a = exp2f(s[2 * kk + 1][0] * SC2);
            float e1b = exp2f(s[2 * kk + 1][1] * SC2);
            float e1c = exp2f(s[2 * kk + 1][2] * SC2);
            float e1d = exp2f(s[2 * kk + 1][3] * SC2);
            rs0 += e0a + e0b + e1a + e1b;
            rs1 += e0c + e0d + e1c + e1d;
            uint32_t a[4];
            a[0] = packbf2(e0a, e0b);
            a[1] = packbf2(e0c, e0d);
            a[2] = packbf2(e1a, e1b);
            a[3] = packbf2(e1c, e1d);

#pragma unroll
            for (int dp = 0; dp < 4; dp++) {
                uint32_t b[4];
                uint32_t addr = vs_b + (uint32_t)((dp * 16 + rowoff) * 272
                                                  + kk * 32 + colsel * 16);
                LDSM_X4(b, addr);
                MMA16816(o[2 * dp],     a, b[0], b[1]);
                MMA16816(o[2 * dp + 1], a, b[2], b[3]);
            }
        }
    }

    rs0 += __shfl_xor_sync(0xFFFFFFFF, rs0, 1);
    rs0 += __shfl_xor_sync(0xFFFFFFFF, rs0, 2);
    rs1 += __shfl_xor_sync(0xFFFFFFFF, rs1, 1);
    rs1 += __shfl_xor_sync(0xFFFFFFFF, rs1, 2);
    const float inv0 = 1.0f / rs0;
    const float inv1 = 1.0f / rs1;

    const int qg0 = q0 + w * 16 + grp;
#pragma unroll
    for (int dt = 0; dt < 8; dt++) {
        int d = dt * 8 + tg * 2;
        size_t i00 = ((size_t)n * CT + h * 64 + d) * LL + qg0;
        size_t i01 = ((size_t)n * CT + h * 64 + d + 1) * LL + qg0;
        g_mid[i00]     = tokens[i00]     + o[dt][0] * inv0;
        g_mid[i01]     = tokens[i01]     + o[dt][1] * inv0;
        g_mid[i00 + 8] = tokens[i00 + 8] + o[dt][2] * inv1;
        g_mid[i01 + 8] = tokens[i01 + 8] + o[dt][3] * inv1;
    }
}

// ---------------------------------------------------------------------------
extern "C" void kernel_launch(void* const* d_in, const int* in_sizes, int n_in,
                              void* d_out, int out_size)
{
    (void)in_sizes; (void)n_in; (void)out_size;
    const float* tokens = (const float*)d_in[0];
    const float* kw = (const float*)d_in[1];
    const float* kb = (const float*)d_in[2];
    const float* kg = (const float*)d_in[3];
    const float* kbe = (const float*)d_in[4];
    const float* km = (const float*)d_in[5];
    const float* kvv = (const float*)d_in[6];
    const float* qw = (const float*)d_in[7];
    const float* qb = (const float*)d_in[8];
    const float* qg = (const float*)d_in[9];
    const float* qbe = (const float*)d_in[10];
    const float* qm = (const float*)d_in[11];
    const float* qvv = (const float*)d_in[12];
    const float* vw = (const float*)d_in[13];
    const float* vb = (const float*)d_in[14];
    const float* vg = (const float*)d_in[15];
    const float* vbe = (const float*)d_in[16];
    const float* vm = (const float*)d_in[17];
    const float* vvv = (const float*)d_in[18];
    const float* fw = (const float*)d_in[19];
    const float* fb = (const float*)d_in[20];
    const float* fg = (const float*)d_in[21];
    const float* fbe = (const float*)d_in[22];
    const float* fm = (const float*)d_in[23];
    const float* fvv = (const float*)d_in[24];

    const int smem64  = (2 * 64 * 36 + 2 * 32 * 136) * 4;    // 53248 B
    const int smem128 = (2 * 128 * 36 + 2 * 32 * 136) * 4;   // 71680 B
    cudaFuncSetAttribute(conv_mma_kernel<64>,
                         cudaFuncAttributeMaxDynamicSharedMemorySize, smem64);
    cudaFuncSetAttribute(conv_mma_kernel<128>,
                         cudaFuncAttributeMaxDynamicSharedMemorySize, smem128);

    // K, Q convs: cout=512, groups=8 -> transposed bf16 [n][h][l][32]
    conv_mma_kernel<64><<<dim3(8, 8, 8), 256, smem64>>>(
        tokens, kw, kb, kg, kbe, km, kvv, nullptr, 0, OUT_KT, 0, 128, 64, 512);
    conv_mma_kernel<64><<<dim3(8, 8, 8), 256, smem64>>>(
        tokens, qw, qb, qg, qbe, qm, qvv, nullptr, 0, OUT_QT, 0, 128, 64, 512);
    // V conv: cout=1024, groups=8 -> bf16 [n][c][l]
    conv_mma_kernel<128><<<dim3(8, 8, 8), 256, smem128>>>(
        tokens, vw, vb, vg, vbe, vm, vvv, nullptr, 0, OUT_VB, 0, 128, 128, 1024);

    // Attention + residual -> g_mid
    attn_mma_kernel<<<dim3(8, HEADS, 8), 256>>>(tokens);

    // FF conv (groups=1, tf32) + residual: g_mid -> d_out
    conv_mma_kernel<128><<<dim3(8, 8, 8), 256, smem128>>>(
        nullptr, fw, fb, fg, fbe, fm, fvv, (float*)d_out, 1, OUT_F32, 1,
        1024, 1024, 1024);
}